// round 7
// baseline (speedup 1.0000x reference)
#include <cuda_runtime.h>
#include <cstdint>

static constexpr int cB  = 2;
static constexpr int cS  = 2048;
static constexpr int cE  = 1024;
static constexpr int cH  = 16;
static constexpr int cHD = 64;

// ---------------- scratch (device globals, allocation-free) ----------------
__device__ float g_qg[cB * cS * cE];
__device__ float g_kg[cB * cS * cE];
__device__ float g_vg[cB * cS * cE];
__device__ float g_qh[cB * cS * cE];
__device__ float g_kh[cB * cS * cE];
__device__ float g_vh[cB * cS * cE];
__device__ float g_at[cB * cS * cE];
__device__ float g_w2q[cE * cE];
__device__ float g_w2k[cE * cE];
__device__ float g_w2v[cE * cE];
__device__ unsigned char g_mask[cB * cS * cS];

// ---------------- helpers ----------------
__device__ __forceinline__ float ftf32(float x) {
    uint32_t u;
    asm("cvt.rna.tf32.f32 %0, %1;" : "=r"(u) : "f"(x));
    return __uint_as_float(u);
}
__device__ __forceinline__ float2 split2(float x) {
    float hi = ftf32(x);
    return make_float2(hi, ftf32(x - hi));
}
__device__ __forceinline__ void mma8(float c[4], const uint32_t a[4], const uint32_t b[2]) {
    asm volatile(
        "mma.sync.aligned.m16n8k8.row.col.f32.tf32.tf32.f32 "
        "{%0,%1,%2,%3}, {%4,%5,%6,%7}, {%8,%9}, {%0,%1,%2,%3};\n"
        : "+f"(c[0]), "+f"(c[1]), "+f"(c[2]), "+f"(c[3])
        : "r"(a[0]), "r"(a[1]), "r"(a[2]), "r"(a[3]), "r"(b[0]), "r"(b[1]));
}

// ---------------- mask normalizer: any dtype -> uint8 0/1 ----------------
// Word-level sniff: int32 words in {0,1}; float32 words in {0, 0x3F800000};
// packed-uint8 words of a random 0/1 mask hit other values within 256 words.
__global__ void mask_convert(const unsigned int* __restrict__ raw,
                             unsigned char* __restrict__ out)
{
    __shared__ int s_wide;
    if (threadIdx.x == 0) {
        int wide = 1;   // 4 bytes per element (int32 or float32)
        #pragma unroll 1
        for (int i = 0; i < 256; i++) {
            const unsigned int w = raw[i];
            if (w != 0u && w != 1u && w != 0x3F800000u) { wide = 0; break; }
        }
        s_wide = wide;
    }
    __syncthreads();
    const int i4 = blockIdx.x * blockDim.x + threadIdx.x;   // group of 4 elements
    if (s_wide) {
        const uint4 w = ((const uint4*)raw)[i4];
        uchar4 r;
        r.x = (w.x != 0u); r.y = (w.y != 0u); r.z = (w.z != 0u); r.w = (w.w != 0u);
        ((uchar4*)out)[i4] = r;
    } else {
        ((unsigned int*)out)[i4] = raw[i4];   // already bytes 0/1
    }
}

// ---------------- repack Wh[H,E,HD] -> W2[E, H*HD] ----------------
__global__ void repack_k(const float* __restrict__ src, float* __restrict__ dst) {
    const int i  = blockIdx.x * 256 + threadIdx.x;   // over H*E*HD = 1<<20
    const int d  = i & 63;
    const int e  = (i >> 6) & 1023;
    const int hh = i >> 16;
    dst[e * cE + hh * cHD + d] = src[i];
}

// ---------------- GEMM: C[4096,1024] = A @ B + bias (3xTF32) ----------------
static constexpr int GLA = 36;    // A smem stride
static constexpr int GLB = 136;   // B smem stride
static constexpr int GSMEM = (2 * 128 * GLA + 2 * 32 * GLB) * 4;  // 71680 B

__global__ __launch_bounds__(256) void gemm_tf32x3(
    const float* __restrict__ A, const float* __restrict__ Bw,
    const float* __restrict__ bias, float* __restrict__ C)
{
    extern __shared__ float sm[];
    float* Ah = sm;                       // 128*36
    float* Al = sm + 128 * GLA;
    float* Bh = sm + 2 * 128 * GLA;       // 32*136
    float* Bl = sm + 2 * 128 * GLA + 32 * GLB;

    const int tid  = threadIdx.x;
    const int lane = tid & 31, wid = tid >> 5;
    const int grp  = lane >> 2, qid = lane & 3;
    const int wm   = (wid & 1) * 64;
    const int wn   = (wid >> 1) * 32;
    const int bm   = blockIdx.y * 128;
    const int bn   = blockIdx.x * 128;

    const int ar = tid >> 3, ac = (tid & 7) * 4;
    const int br = tid >> 5, bc = (tid & 31) * 4;

    float acc[4][4][4];
    #pragma unroll
    for (int i = 0; i < 4; i++)
        #pragma unroll
        for (int j = 0; j < 4; j++)
            #pragma unroll
            for (int t = 0; t < 4; t++) acc[i][j][t] = 0.f;

    float4 ra[4], rb[4];

    auto load_regs = [&](int k0) {
        #pragma unroll
        for (int i = 0; i < 4; i++)
            ra[i] = *(const float4*)(A + (size_t)(bm + ar + 32 * i) * cE + k0 + ac);
        #pragma unroll
        for (int i = 0; i < 4; i++)
            rb[i] = *(const float4*)(Bw + (size_t)(k0 + br + 8 * i) * cE + bn + bc);
    };
    auto store_split = [&]() {
        #pragma unroll
        for (int i = 0; i < 4; i++) {
            float2 s0 = split2(ra[i].x), s1 = split2(ra[i].y);
            float2 s2 = split2(ra[i].z), s3 = split2(ra[i].w);
            *(float4*)(Ah + (ar + 32 * i) * GLA + ac) = make_float4(s0.x, s1.x, s2.x, s3.x);
            *(float4*)(Al + (ar + 32 * i) * GLA + ac) = make_float4(s0.y, s1.y, s2.y, s3.y);
        }
        #pragma unroll
        for (int i = 0; i < 4; i++) {
            float2 s0 = split2(rb[i].x), s1 = split2(rb[i].y);
            float2 s2 = split2(rb[i].z), s3 = split2(rb[i].w);
            *(float4*)(Bh + (br + 8 * i) * GLB + bc) = make_float4(s0.x, s1.x, s2.x, s3.x);
            *(float4*)(Bl + (br + 8 * i) * GLB + bc) = make_float4(s0.y, s1.y, s2.y, s3.y);
        }
    };

    load_regs(0);
    store_split();
    __syncthreads();

    for (int kt = 1; kt <= 32; kt++) {
        if (kt < 32) load_regs(kt * 32);
        #pragma unroll
        for (int ks = 0; ks < 4; ks++) {
            const int kk = ks * 8;
            uint32_t bh[4][2], bl[4][2];
            #pragma unroll
            for (int ni = 0; ni < 4; ni++) {
                const int n = wn + ni * 8 + grp;
                bh[ni][0] = __float_as_uint(Bh[(kk + qid) * GLB + n]);
                bh[ni][1] = __float_as_uint(Bh[(kk + qid + 4) * GLB + n]);
                bl[ni][0] = __float_as_uint(Bl[(kk + qid) * GLB + n]);
                bl[ni][1] = __float_as_uint(Bl[(kk + qid + 4) * GLB + n]);
            }
            #pragma unroll
            for (int mi = 0; mi < 4; mi++) {
                const int r = wm + mi * 16 + grp;
                uint32_t ah[4], al[4];
                ah[0] = __float_as_uint(Ah[r * GLA + kk + qid]);
                ah[1] = __float_as_uint(Ah[(r + 8) * GLA + kk + qid]);
                ah[2] = __float_as_uint(Ah[r * GLA + kk + qid + 4]);
                ah[3] = __float_as_uint(Ah[(r + 8) * GLA + kk + qid + 4]);
                al[0] = __float_as_uint(Al[r * GLA + kk + qid]);
                al[1] = __float_as_uint(Al[(r + 8) * GLA + kk + qid]);
                al[2] = __float_as_uint(Al[r * GLA + kk + qid + 4]);
                al[3] = __float_as_uint(Al[(r + 8) * GLA + kk + qid + 4]);
                #pragma unroll
                for (int ni = 0; ni < 4; ni++) {
                    mma8(acc[mi][ni], ah, bh[ni]);
                    mma8(acc[mi][ni], al, bh[ni]);
                    mma8(acc[mi][ni], ah, bl[ni]);
                }
            }
        }
        __syncthreads();
        if (kt < 32) { store_split(); __syncthreads(); }
    }

    #pragma unroll
    for (int mi = 0; mi < 4; mi++) {
        const int r = bm + wm + mi * 16 + grp;
        #pragma unroll
        for (int ni = 0; ni < 4; ni++) {
            const int col = bn + wn + ni * 8 + 2 * qid;
            const float2 bv = *(const float2*)(bias + col);
            float2 t0 = make_float2(acc[mi][ni][0] + bv.x, acc[mi][ni][1] + bv.y);
            *(float2*)(C + (size_t)r * cE + col) = t0;
            float2 t1 = make_float2(acc[mi][ni][2] + bv.x, acc[mi][ni][3] + bv.y);
            *(float2*)(C + (size_t)(r + 8) * cE + col) = t1;
        }
    }
}

// ---------------- flash attention (Br=Bc=64, HD=64, 4 warps) ----------------
static constexpr int ASMEM = (4 * 64 * 68 + 64 * 72) * 4 + 64 * 64;  // 92160 B

__global__ __launch_bounds__(128) void flash_attn(
    const float* __restrict__ Qm, const float* __restrict__ Km,
    const float* __restrict__ Vm, const unsigned char* __restrict__ Mask,
    float* __restrict__ Om)
{
    extern __shared__ float sm[];
    float* Qh = sm;
    float* Ql = sm + 4352;
    float* Kh = sm + 8704;
    float* Kl = sm + 13056;
    float* Vs = sm + 17408;
    unsigned char* Ms = (unsigned char*)(sm + 22016);
    float* Ps = Kh;  // alias: safe with syncs below

    const int tid = threadIdx.x, lane = tid & 31, w = tid >> 5;
    const int grp = lane >> 2, qid = lane & 3;
    const int b = blockIdx.y >> 4, h = blockIdx.y & 15;
    const int r0 = blockIdx.x * 64;

    const float* qb = Qm + (size_t)b * cS * cE + h * cHD;
    const float* kb = Km + (size_t)b * cS * cE + h * cHD;
    const float* vb = Vm + (size_t)b * cS * cE + h * cHD;
    const unsigned char* mb = Mask + (size_t)b * cS * cS;

    {   // Q tile, split
        const int rw = tid >> 4, cc = (tid & 15) * 4;
        #pragma unroll
        for (int i = 0; i < 8; i++) {
            const int r = rw + 8 * i;
            float4 t = *(const float4*)(qb + (size_t)(r0 + r) * cE + cc);
            float2 s0 = split2(t.x), s1 = split2(t.y), s2 = split2(t.z), s3 = split2(t.w);
            *(float4*)(Qh + r * 68 + cc) = make_float4(s0.x, s1.x, s2.x, s3.x);
            *(float4*)(Ql + r * 68 + cc) = make_float4(s0.y, s1.y, s2.y, s3.y);
        }
    }

    const float NEG = -1e24f;
    float m0 = NEG, m1 = NEG, l0 = 0.f, l1 = 0.f;
    float o[8][4];
    #pragma unroll
    for (int i = 0; i < 8; i++)
        #pragma unroll
        for (int j = 0; j < 4; j++) o[i][j] = 0.f;

    const int rr0 = w * 16 + grp, rr1 = rr0 + 8;

    for (int jt = 0; jt < 32; jt++) {
        __syncthreads();  // prior P reads done before K overwrite
        {
            const int rw = tid >> 4, cc = (tid & 15) * 4;
            #pragma unroll
            for (int i = 0; i < 8; i++) {
                const int r = rw + 8 * i;
                float4 t = *(const float4*)(kb + (size_t)(jt * 64 + r) * cE + cc);
                float2 s0 = split2(t.x), s1 = split2(t.y), s2 = split2(t.z), s3 = split2(t.w);
                *(float4*)(Kh + r * 68 + cc) = make_float4(s0.x, s1.x, s2.x, s3.x);
                *(float4*)(Kl + r * 68 + cc) = make_float4(s0.y, s1.y, s2.y, s3.y);
                float4 tv = *(const float4*)(vb + (size_t)(jt * 64 + r) * cE + cc);
                *(float4*)(Vs + r * 72 + cc) =
                    make_float4(ftf32(tv.x), ftf32(tv.y), ftf32(tv.z), ftf32(tv.w));
            }
            const int mr = tid >> 2, mc = (tid & 3) * 16;
            *(int4*)(Ms + mr * 64 + mc) =
                *(const int4*)(mb + (size_t)(r0 + mr) * cS + jt * 64 + mc);
            *(int4*)(Ms + (mr + 32) * 64 + mc) =
                *(const int4*)(mb + (size_t)(r0 + mr + 32) * cS + jt * 64 + mc);
        }
        __syncthreads();

        // S = Q @ K^T (3xTF32)
        float sf[8][4];
        #pragma unroll
        for (int i = 0; i < 8; i++)
            #pragma unroll
            for (int j = 0; j < 4; j++) sf[i][j] = 0.f;

        #pragma unroll
        for (int ks = 0; ks < 8; ks++) {
            const int kk = ks * 8;
            uint32_t ah[4], al[4];
            ah[0] = __float_as_uint(Qh[rr0 * 68 + kk + qid]);
            ah[1] = __float_as_uint(Qh[rr1 * 68 + kk + qid]);
            ah[2] = __float_as_uint(Qh[rr0 * 68 + kk + qid + 4]);
            ah[3] = __float_as_uint(Qh[rr1 * 68 + kk + qid + 4]);
            al[0] = __float_as_uint(Ql[rr0 * 68 + kk + qid]);
            al[1] = __float_as_uint(Ql[rr1 * 68 + kk + qid]);
            al[2] = __float_as_uint(Ql[rr0 * 68 + kk + qid + 4]);
            al[3] = __float_as_uint(Ql[rr1 * 68 + kk + qid + 4]);
            #pragma unroll
            for (int nt = 0; nt < 8; nt++) {
                const int n = nt * 8 + grp;
                uint32_t bh[2], bl[2];
                bh[0] = __float_as_uint(Kh[n * 68 + kk + qid]);
                bh[1] = __float_as_uint(Kh[n * 68 + kk + qid + 4]);
                bl[0] = __float_as_uint(Kl[n * 68 + kk + qid]);
                bl[1] = __float_as_uint(Kl[n * 68 + kk + qid + 4]);
                mma8(sf[nt], ah, bh);
                mma8(sf[nt], al, bh);
                mma8(sf[nt], ah, bl);
            }
        }

        // scale, mask, online softmax
        float tm0 = NEG, tm1 = NEG;
        #pragma unroll
        for (int nt = 0; nt < 8; nt++) {
            const int cb = nt * 8 + 2 * qid;
            float v0 = sf[nt][0] * 0.125f; if (Ms[rr0 * 64 + cb])     v0 = NEG;
            float v1 = sf[nt][1] * 0.125f; if (Ms[rr0 * 64 + cb + 1]) v1 = NEG;
            float v2 = sf[nt][2] * 0.125f; if (Ms[rr1 * 64 + cb])     v2 = NEG;
            float v3 = sf[nt][3] * 0.125f; if (Ms[rr1 * 64 + cb + 1]) v3 = NEG;
            sf[nt][0] = v0; sf[nt][1] = v1; sf[nt][2] = v2; sf[nt][3] = v3;
            tm0 = fmaxf(tm0, fmaxf(v0, v1));
            tm1 = fmaxf(tm1, fmaxf(v2, v3));
        }
        tm0 = fmaxf(tm0, __shfl_xor_sync(0xffffffffu, tm0, 1));
        tm0 = fmaxf(tm0, __shfl_xor_sync(0xffffffffu, tm0, 2));
        tm1 = fmaxf(tm1, __shfl_xor_sync(0xffffffffu, tm1, 1));
        tm1 = fmaxf(tm1, __shfl_xor_sync(0xffffffffu, tm1, 2));

        const float mn0 = fmaxf(m0, tm0), mn1 = fmaxf(m1, tm1);
        const float cor0 = __expf(m0 - mn0), cor1 = __expf(m1 - mn1);
        m0 = mn0; m1 = mn1;

        float rs0 = 0.f, rs1 = 0.f;
        #pragma unroll
        for (int nt = 0; nt < 8; nt++) {
            float p0 = __expf(sf[nt][0] - m0);
            float p1 = __expf(sf[nt][1] - m0);
            float p2 = __expf(sf[nt][2] - m1);
            float p3 = __expf(sf[nt][3] - m1);
            sf[nt][0] = p0; sf[nt][1] = p1; sf[nt][2] = p2; sf[nt][3] = p3;
            rs0 += p0 + p1; rs1 += p2 + p3;
        }
        rs0 += __shfl_xor_sync(0xffffffffu, rs0, 1);
        rs0 += __shfl_xor_sync(0xffffffffu, rs0, 2);
        rs1 += __shfl_xor_sync(0xffffffffu, rs1, 1);
        rs1 += __shfl_xor_sync(0xffffffffu, rs1, 2);
        l0 = l0 * cor0 + rs0;
        l1 = l1 * cor1 + rs1;

        #pragma unroll
        for (int nt = 0; nt < 8; nt++) {
            o[nt][0] *= cor0; o[nt][1] *= cor0;
            o[nt][2] *= cor1; o[nt][3] *= cor1;
        }

        __syncthreads();  // all Kh reads done before P write
        #pragma unroll
        for (int nt = 0; nt < 8; nt++) {
            const int cb = nt * 8 + 2 * qid;
            *(float2*)(Ps + rr0 * 68 + cb) = make_float2(ftf32(sf[nt][0]), ftf32(sf[nt][1]));
            *(float2*)(Ps + rr1 * 68 + cb) = make_float2(ftf32(sf[nt][2]), ftf32(sf[nt][3]));
        }
        __syncthreads();

        // O += P @ V
        #pragma unroll
        for (int ks = 0; ks < 8; ks++) {
            const int kk = ks * 8;
            uint32_t af[4];
            af[0] = __float_as_uint(Ps[rr0 * 68 + kk + qid]);
            af[1] = __float_as_uint(Ps[rr1 * 68 + kk + qid]);
            af[2] = __float_as_uint(Ps[rr0 * 68 + kk + qid + 4]);
            af[3] = __float_as_uint(Ps[rr1 * 68 + kk + qid + 4]);
            #pragma unroll
            for (int nt = 0; nt < 8; nt++) {
                uint32_t bf[2];
                bf[0] = __float_as_uint(Vs[(kk + qid) * 72 + nt * 8 + grp]);
                bf[1] = __float_as_uint(Vs[(kk + qid + 4) * 72 + nt * 8 + grp]);
                mma8(o[nt], af, bf);
            }
        }
    }

    const float inv0 = 1.f / l0, inv1 = 1.f / l1;
    float* ob = Om + (size_t)b * cS * cE + h * cHD;
    #pragma unroll
    for (int nt = 0; nt < 8; nt++) {
        const int col = nt * 8 + 2 * qid;
        *(float2*)(ob + (size_t)(r0 + rr0) * cE + col) =
            make_float2(o[nt][0] * inv0, o[nt][1] * inv0);
        *(float2*)(ob + (size_t)(r0 + rr1) * cE + col) =
            make_float2(o[nt][2] * inv1, o[nt][3] * inv1);
    }
}

// ---------------- launcher ----------------
extern "C" void kernel_launch(void* const* d_in, const int* in_sizes, int n_in,
                              void* d_out, int out_size)
{
    const float* q   = (const float*)d_in[0];
    const float* k   = (const float*)d_in[1];
    const float* v   = (const float*)d_in[2];
    const unsigned int* mask_raw = (const unsigned int*)d_in[3];
    const float* Wq  = (const float*)d_in[4];
    const float* bq  = (const float*)d_in[5];
    const float* Wk  = (const float*)d_in[6];
    const float* bk  = (const float*)d_in[7];
    const float* Wv  = (const float*)d_in[8];
    const float* bv  = (const float*)d_in[9];
    const float* Whq = (const float*)d_in[10];
    const float* bhq = (const float*)d_in[11];
    const float* Whk = (const float*)d_in[12];
    const float* bhk = (const float*)d_in[13];
    const float* Whv = (const float*)d_in[14];
    const float* bhv = (const float*)d_in[15];
    const float* Wo  = (const float*)d_in[16];
    const float* bo  = (const float*)d_in[17];
    float* out = (float*)d_out;

    float *p_qg, *p_kg, *p_vg, *p_qh, *p_kh, *p_vh, *p_at, *p_w2q, *p_w2k, *p_w2v;
    unsigned char* p_mask;
    cudaGetSymbolAddress((void**)&p_qg, g_qg);
    cudaGetSymbolAddress((void**)&p_kg, g_kg);
    cudaGetSymbolAddress((void**)&p_vg, g_vg);
    cudaGetSymbolAddress((void**)&p_qh, g_qh);
    cudaGetSymbolAddress((void**)&p_kh, g_kh);
    cudaGetSymbolAddress((void**)&p_vh, g_vh);
    cudaGetSymbolAddress((void**)&p_at, g_at);
    cudaGetSymbolAddress((void**)&p_w2q, g_w2q);
    cudaGetSymbolAddress((void**)&p_w2k, g_w2k);
    cudaGetSymbolAddress((void**)&p_w2v, g_w2v);
    cudaGetSymbolAddress((void**)&p_mask, g_mask);

    cudaFuncSetAttribute(gemm_tf32x3, cudaFuncAttributeMaxDynamicSharedMemorySize, GSMEM);
    cudaFuncSetAttribute(flash_attn,  cudaFuncAttributeMaxDynamicSharedMemorySize, ASMEM);

    const dim3 gg(8, 32);   // N/128, M/128

    // mask: 8M elements, 4 per thread
    mask_convert<<<(cB * cS * cS) / 4 / 256, 256>>>(mask_raw, p_mask);

    repack_k<<<4096, 256>>>(Whq, p_w2q);
    repack_k<<<4096, 256>>>(Whk, p_w2k);
    repack_k<<<4096, 256>>>(Whv, p_w2v);

    gemm_tf32x3<<<gg, 256, GSMEM>>>(q, Wq, bq, p_qg);
    gemm_tf32x3<<<gg, 256, GSMEM>>>(k, Wk, bk, p_kg);
    gemm_tf32x3<<<gg, 256, GSMEM>>>(v, Wv, bv, p_vg);

    gemm_tf32x3<<<gg, 256, GSMEM>>>(p_qg, p_w2q, bhq, p_qh);
    gemm_tf32x3<<<gg, 256, GSMEM>>>(p_kg, p_w2k, bhk, p_kh);
    gemm_tf32x3<<<gg, 256, GSMEM>>>(p_vg, p_w2v, bhv, p_vh);

    flash_attn<<<dim3(32, 32), 128, ASMEM>>>(p_qh, p_kh, p_vh, p_mask, p_at);

    gemm_tf32x3<<<gg, 256, GSMEM>>>(p_at, Wo, bo, out);
}

// round 9
// speedup vs baseline: 1.5410x; 1.5410x over previous
#include <cuda_runtime.h>
#include <cuda_bf16.h>
#include <cstdint>

static constexpr int cB  = 2;
static constexpr int cS  = 2048;
static constexpr int cE  = 1024;
static constexpr int cH  = 16;
static constexpr int cHD = 64;

// ---------------- scratch (device globals, allocation-free) ----------------
__device__ float g_qg[cB * cS * cE];
__device__ float g_kg[cB * cS * cE];
__device__ float g_vg[cB * cS * cE];
__device__ float g_qh[cB * cS * cE];
__device__ float g_kh[cB * cS * cE];
__device__ float g_vh[cB * cS * cE];
__device__ float g_at[cB * cS * cE];
__device__ unsigned char g_mask[cB * cS * cS];
// pre-split transposed weights: [n][k] bf16 hi/lo
__device__ __nv_bfloat16 g_wh_q[cE * cE],  g_wl_q[cE * cE];
__device__ __nv_bfloat16 g_wh_k[cE * cE],  g_wl_k[cE * cE];
__device__ __nv_bfloat16 g_wh_v[cE * cE],  g_wl_v[cE * cE];
__device__ __nv_bfloat16 g_wh_o[cE * cE],  g_wl_o[cE * cE];
__device__ __nv_bfloat16 g_wh_hq[cE * cE], g_wl_hq[cE * cE];
__device__ __nv_bfloat16 g_wh_hk[cE * cE], g_wl_hk[cE * cE];
__device__ __nv_bfloat16 g_wh_hv[cE * cE], g_wl_hv[cE * cE];

// ---------------- helpers ----------------
__device__ __forceinline__ float ftf32(float x) {
    uint32_t u;
    asm("cvt.rna.tf32.f32 %0, %1;" : "=r"(u) : "f"(x));
    return __uint_as_float(u);
}
__device__ __forceinline__ void splitbf(float x, unsigned short& h, unsigned short& l) {
    __nv_bfloat16 bh = __float2bfloat16(x);
    float r = x - __bfloat162float(bh);
    h = __bfloat16_as_ushort(bh);
    l = __bfloat16_as_ushort(__float2bfloat16(r));
}
__device__ __forceinline__ uint32_t pack2(unsigned short a, unsigned short b) {
    return (uint32_t)a | ((uint32_t)b << 16);
}
// tf32 m16n8k8 (used by PV only)
__device__ __forceinline__ void mma8(float c[4], const uint32_t a[4], const uint32_t b[2]) {
    asm volatile(
        "mma.sync.aligned.m16n8k8.row.col.f32.tf32.tf32.f32 "
        "{%0,%1,%2,%3}, {%4,%5,%6,%7}, {%8,%9}, {%0,%1,%2,%3};\n"
        : "+f"(c[0]), "+f"(c[1]), "+f"(c[2]), "+f"(c[3])
        : "r"(a[0]), "r"(a[1]), "r"(a[2]), "r"(a[3]), "r"(b[0]), "r"(b[1]));
}
// bf16 m16n8k16
__device__ __forceinline__ void mma16(float c[4], const uint32_t a[4], const uint32_t b[2]) {
    asm volatile(
        "mma.sync.aligned.m16n8k16.row.col.f32.bf16.bf16.f32 "
        "{%0,%1,%2,%3}, {%4,%5,%6,%7}, {%8,%9}, {%0,%1,%2,%3};\n"
        : "+f"(c[0]), "+f"(c[1]), "+f"(c[2]), "+f"(c[3])
        : "r"(a[0]), "r"(a[1]), "r"(a[2]), "r"(a[3]), "r"(b[0]), "r"(b[1]));
}

// ---------------- mask normalizer: any dtype -> uint8 0/1 ----------------
__global__ void mask_convert(const unsigned int* __restrict__ raw,
                             unsigned char* __restrict__ out)
{
    __shared__ int s_wide;
    if (threadIdx.x == 0) {
        int wide = 1;
        #pragma unroll 1
        for (int i = 0; i < 256; i++) {
            const unsigned int w = raw[i];
            if (w != 0u && w != 1u && w != 0x3F800000u) { wide = 0; break; }
        }
        s_wide = wide;
    }
    __syncthreads();
    const int i4 = blockIdx.x * blockDim.x + threadIdx.x;
    if (s_wide) {
        const uint4 w = ((const uint4*)raw)[i4];
        uchar4 r;
        r.x = (w.x != 0u); r.y = (w.y != 0u); r.z = (w.z != 0u); r.w = (w.w != 0u);
        ((uchar4*)out)[i4] = r;
    } else {
        ((unsigned int*)out)[i4] = raw[i4];
    }
}

// ---------------- weight prep: W[k][n] -> Th/Tl[n][k] (bf16 split) --------
__global__ void prep_w(const float* __restrict__ W,
                       __nv_bfloat16* __restrict__ Th, __nv_bfloat16* __restrict__ Tl)
{
    __shared__ float t[32][33];
    const int tx = threadIdx.x & 31, ty = threadIdx.x >> 5;
    const int k0 = blockIdx.y * 32, n0 = blockIdx.x * 32;
    #pragma unroll
    for (int i = 0; i < 4; i++)
        t[ty + 8 * i][tx] = W[(size_t)(k0 + ty + 8 * i) * cE + n0 + tx];
    __syncthreads();
    #pragma unroll
    for (int i = 0; i < 4; i++) {
        const float v = t[tx][ty + 8 * i];
        __nv_bfloat16 h = __float2bfloat16(v);
        const size_t o = (size_t)(n0 + ty + 8 * i) * cE + k0 + tx;
        Th[o] = h;
        Tl[o] = __float2bfloat16(v - __bfloat162float(h));
    }
}
// Wh[h][e][d] -> Th/Tl[n = h*64+d][k = e]
__global__ void prep_wh(const float* __restrict__ W,
                        __nv_bfloat16* __restrict__ Th, __nv_bfloat16* __restrict__ Tl)
{
    __shared__ float t[32][33];
    const int tx = threadIdx.x & 31, ty = threadIdx.x >> 5;
    const int d0 = blockIdx.x * 32, e0 = blockIdx.y * 32, h = blockIdx.z;
    #pragma unroll
    for (int i = 0; i < 4; i++)
        t[ty + 8 * i][tx] = W[(size_t)(h * cE + e0 + ty + 8 * i) * cHD + d0 + tx];
    __syncthreads();
    #pragma unroll
    for (int i = 0; i < 4; i++) {
        const float v = t[tx][ty + 8 * i];
        __nv_bfloat16 hh = __float2bfloat16(v);
        const size_t o = (size_t)(h * cHD + d0 + ty + 8 * i) * cE + e0 + tx;
        Th[o] = hh;
        Tl[o] = __float2bfloat16(v - __bfloat162float(hh));
    }
}

// ---------------- GEMM: C[4096,1024] = A @ B + bias (bf16x3) ---------------
// BM=128, BN=128, BK=32; smem stride 40 halves (20 words, ==4 mod 8 -> no bank conflicts)
static constexpr int GBUF = 40960;            // 4 arrays * 128*40*2B
static constexpr int GSMEM = 2 * GBUF;        // 81920 B double-buffered

__global__ __launch_bounds__(256) void gemm_bf16x3(
    const float* __restrict__ A,
    const __nv_bfloat16* __restrict__ Bth, const __nv_bfloat16* __restrict__ Btl,
    const float* __restrict__ bias, float* __restrict__ C)
{
    extern __shared__ char smc[];
    const int tid  = threadIdx.x;
    const int lane = tid & 31, wid = tid >> 5;
    const int grp  = lane >> 2, qid = lane & 3;
    const int wm   = (wid & 1) * 64;
    const int wn   = (wid >> 1) * 32;
    const int bm   = blockIdx.y * 128;
    const int bn   = blockIdx.x * 128;
    const int fr   = tid >> 3, fc = (tid & 7) * 4;

    float acc[4][4][4];
    #pragma unroll
    for (int i = 0; i < 4; i++)
        #pragma unroll
        for (int j = 0; j < 4; j++)
            #pragma unroll
            for (int t = 0; t < 4; t++) acc[i][j][t] = 0.f;

    float4 ra[4]; uint2 rbh[4], rbl[4];

    auto load_regs = [&](int k0) {
        #pragma unroll
        for (int i = 0; i < 4; i++)
            ra[i] = *(const float4*)(A + (size_t)(bm + fr + 32 * i) * cE + k0 + fc);
        #pragma unroll
        for (int i = 0; i < 4; i++) {
            const size_t off = (size_t)(bn + fr + 32 * i) * cE + k0 + fc;
            rbh[i] = *(const uint2*)(Bth + off);
            rbl[i] = *(const uint2*)(Btl + off);
        }
    };
    auto store_buf = [&](int b) {
        char* base = smc + b * GBUF;
        #pragma unroll
        for (int i = 0; i < 4; i++) {
            unsigned short h0, l0, h1, l1, h2, l2, h3, l3;
            splitbf(ra[i].x, h0, l0); splitbf(ra[i].y, h1, l1);
            splitbf(ra[i].z, h2, l2); splitbf(ra[i].w, h3, l3);
            uint2 wh; wh.x = pack2(h0, h1); wh.y = pack2(h2, h3);
            uint2 wl; wl.x = pack2(l0, l1); wl.y = pack2(l2, l3);
            const int o = ((fr + 32 * i) * 40 + fc) * 2;
            *(uint2*)(base + o)         = wh;
            *(uint2*)(base + 10240 + o) = wl;
        }
        #pragma unroll
        for (int i = 0; i < 4; i++) {
            const int o = ((fr + 32 * i) * 40 + fc) * 2;
            *(uint2*)(base + 20480 + o) = rbh[i];
            *(uint2*)(base + 30720 + o) = rbl[i];
        }
    };
    auto compute = [&](int b) {
        const char* base = smc + b * GBUF;
        const char* Ah = base;
        const char* Al = base + 10240;
        const char* Bh = base + 20480;
        const char* Bl = base + 30720;
        #pragma unroll
        for (int chunk = 0; chunk < 2; chunk++) {
            const int hb = chunk * 16 + 2 * qid;
            uint32_t bh[4][2], bl[4][2];
            #pragma unroll
            for (int ni = 0; ni < 4; ni++) {
                const int n = wn + ni * 8 + grp;
                bh[ni][0] = *(const uint32_t*)(Bh + (n * 40 + hb) * 2);
                bh[ni][1] = *(const uint32_t*)(Bh + (n * 40 + hb + 8) * 2);
                bl[ni][0] = *(const uint32_t*)(Bl + (n * 40 + hb) * 2);
                bl[ni][1] = *(const uint32_t*)(Bl + (n * 40 + hb + 8) * 2);
            }
            #pragma unroll
            for (int mi = 0; mi < 4; mi++) {
                const int r = wm + mi * 16 + grp;
                uint32_t ah[4], al[4];
                ah[0] = *(const uint32_t*)(Ah + (r * 40 + hb) * 2);
                ah[1] = *(const uint32_t*)(Ah + ((r + 8) * 40 + hb) * 2);
                ah[2] = *(const uint32_t*)(Ah + (r * 40 + hb + 8) * 2);
                ah[3] = *(const uint32_t*)(Ah + ((r + 8) * 40 + hb + 8) * 2);
                al[0] = *(const uint32_t*)(Al + (r * 40 + hb) * 2);
                al[1] = *(const uint32_t*)(Al + ((r + 8) * 40 + hb) * 2);
                al[2] = *(const uint32_t*)(Al + (r * 40 + hb + 8) * 2);
                al[3] = *(const uint32_t*)(Al + ((r + 8) * 40 + hb + 8) * 2);
                #pragma unroll
                for (int ni = 0; ni < 4; ni++) {
                    mma16(acc[mi][ni], ah, bh[ni]);
                    mma16(acc[mi][ni], al, bh[ni]);
                    mma16(acc[mi][ni], ah, bl[ni]);
                }
            }
        }
    };

    load_regs(0);
    store_buf(0);
    __syncthreads();
    for (int kt = 0; kt < 32; kt++) {
        if (kt < 31) load_regs((kt + 1) * 32);
        compute(kt & 1);
        if (kt < 31) { store_buf((kt + 1) & 1); __syncthreads(); }
    }

    #pragma unroll
    for (int mi = 0; mi < 4; mi++) {
        const int r = bm + wm + mi * 16 + grp;
        #pragma unroll
        for (int ni = 0; ni < 4; ni++) {
            const int col = bn + wn + ni * 8 + 2 * qid;
            const float2 bv = *(const float2*)(bias + col);
            float2 t0 = make_float2(acc[mi][ni][0] + bv.x, acc[mi][ni][1] + bv.y);
            *(float2*)(C + (size_t)r * cE + col) = t0;
            float2 t1 = make_float2(acc[mi][ni][2] + bv.x, acc[mi][ni][3] + bv.y);
            *(float2*)(C + (size_t)(r + 8) * cE + col) = t1;
        }
    }
}

// ---------------- flash attention (Br=Bc=64, HD=64, 4 warps) ----------------
// smem layout (bytes):
//   Qh bf16 [64][72]    @ 0      (9216)
//   Ql bf16 [64][72]    @ 9216
//   Kh bf16 [64][72]    @ 18432   <- Ps fp32 [64][68] aliases [18432, 35840)
//   Kl bf16 [64][72]    @ 27648
//   Vs f32  [64][72]    @ 36864  (18432)
//   Ms u8   [64][64]    @ 55296  (4096)
static constexpr int ASMEM = 59392;

__global__ __launch_bounds__(128) void flash_attn(
    const float* __restrict__ Qm, const float* __restrict__ Km,
    const float* __restrict__ Vm, const unsigned char* __restrict__ Mask,
    float* __restrict__ Om)
{
    extern __shared__ char smc[];
    char* Qh = smc;
    char* Ql = smc + 9216;
    char* Kh = smc + 18432;
    char* Kl = smc + 27648;
    float* Vs = (float*)(smc + 36864);
    unsigned char* Ms = (unsigned char*)(smc + 55296);
    float* Ps = (float*)(smc + 18432);

    const int tid = threadIdx.x, lane = tid & 31, w = tid >> 5;
    const int grp = lane >> 2, qid = lane & 3;
    const int b = blockIdx.y >> 4, h = blockIdx.y & 15;
    const int r0 = blockIdx.x * 64;

    const float* qb = Qm + (size_t)b * cS * cE + h * cHD;
    const float* kb = Km + (size_t)b * cS * cE + h * cHD;
    const float* vb = Vm + (size_t)b * cS * cE + h * cHD;
    const unsigned char* mb = Mask + (size_t)b * cS * cS;

    {   // Q tile, bf16 split
        const int rw = tid >> 4, cc = (tid & 15) * 4;
        #pragma unroll
        for (int i = 0; i < 8; i++) {
            const int r = rw + 8 * i;
            float4 t = *(const float4*)(qb + (size_t)(r0 + r) * cE + cc);
            unsigned short h0, l0, h1, l1, h2, l2, h3, l3;
            splitbf(t.x, h0, l0); splitbf(t.y, h1, l1);
            splitbf(t.z, h2, l2); splitbf(t.w, h3, l3);
            uint2 wh; wh.x = pack2(h0, h1); wh.y = pack2(h2, h3);
            uint2 wl; wl.x = pack2(l0, l1); wl.y = pack2(l2, l3);
            const int o = (r * 72 + cc) * 2;
            *(uint2*)(Qh + o) = wh;
            *(uint2*)(Ql + o) = wl;
        }
    }

    const float NEG = -1e24f;
    float m0 = NEG, m1 = NEG, l0 = 0.f, l1 = 0.f;
    float o[8][4];
    #pragma unroll
    for (int i = 0; i < 8; i++)
        #pragma unroll
        for (int j = 0; j < 4; j++) o[i][j] = 0.f;

    const int rr0 = w * 16 + grp, rr1 = rr0 + 8;

    for (int jt = 0; jt < 32; jt++) {
        __syncthreads();  // prior P reads done before K overwrite
        {
            const int rw = tid >> 4, cc = (tid & 15) * 4;
            #pragma unroll
            for (int i = 0; i < 8; i++) {
                const int r = rw + 8 * i;
                float4 t = *(const float4*)(kb + (size_t)(jt * 64 + r) * cE + cc);
                unsigned short h0, l0b, h1, l1b, h2, l2b, h3, l3b;
                splitbf(t.x, h0, l0b); splitbf(t.y, h1, l1b);
                splitbf(t.z, h2, l2b); splitbf(t.w, h3, l3b);
                uint2 wh; wh.x = pack2(h0, h1); wh.y = pack2(h2, h3);
                uint2 wl; wl.x = pack2(l0b, l1b); wl.y = pack2(l2b, l3b);
                const int ob = (r * 72 + cc) * 2;
                *(uint2*)(Kh + ob) = wh;
                *(uint2*)(Kl + ob) = wl;
                float4 tv = *(const float4*)(vb + (size_t)(jt * 64 + r) * cE + cc);
                *(float4*)(Vs + r * 72 + cc) =
                    make_float4(ftf32(tv.x), ftf32(tv.y), ftf32(tv.z), ftf32(tv.w));
            }
            const int mr = tid >> 2, mc = (tid & 3) * 16;
            *(int4*)(Ms + mr * 64 + mc) =
                *(const int4*)(mb + (size_t)(r0 + mr) * cS + jt * 64 + mc);
            *(int4*)(Ms + (mr + 32) * 64 + mc) =
                *(const int4*)(mb + (size_t)(r0 + mr + 32) * cS + jt * 64 + mc);
        }
        __syncthreads();

        // S = Q @ K^T (bf16x3)
        float sf[8][4];
        #pragma unroll
        for (int i = 0; i < 8; i++)
            #pragma unroll
            for (int j = 0; j < 4; j++) sf[i][j] = 0.f;

        #pragma unroll
        for (int chunk = 0; chunk < 4; chunk++) {
            const int hb = chunk * 16 + 2 * qid;
            uint32_t ah[4], al[4];
            ah[0] = *(const uint32_t*)(Qh + (rr0 * 72 + hb) * 2);
            ah[1] = *(const uint32_t*)(Qh + (rr1 * 72 + hb) * 2);
            ah[2] = *(const uint32_t*)(Qh + (rr0 * 72 + hb + 8) * 2);
            ah[3] = *(const uint32_t*)(Qh + (rr1 * 72 + hb + 8) * 2);
            al[0] = *(const uint32_t*)(Ql + (rr0 * 72 + hb) * 2);
            al[1] = *(const uint32_t*)(Ql + (rr1 * 72 + hb) * 2);
            al[2] = *(const uint32_t*)(Ql + (rr0 * 72 + hb + 8) * 2);
            al[3] = *(const uint32_t*)(Ql + (rr1 * 72 + hb + 8) * 2);
            #pragma unroll
            for (int nt = 0; nt < 8; nt++) {
                const int n = nt * 8 + grp;
                uint32_t bh[2], bl[2];
                bh[0] = *(const uint32_t*)(Kh + (n * 72 + hb) * 2);
                bh[1] = *(const uint32_t*)(Kh + (n * 72 + hb + 8) * 2);
                bl[0] = *(const uint32_t*)(Kl + (n * 72 + hb) * 2);
                bl[1] = *(const uint32_t*)(Kl + (n * 72 + hb + 8) * 2);
                mma16(sf[nt], ah, bh);
                mma16(sf[nt], al, bh);
                mma16(sf[nt], ah, bl);
            }
        }

        // scale, mask, online softmax
        float tm0 = NEG, tm1 = NEG;
        #pragma unroll
        for (int nt = 0; nt < 8; nt++) {
            const int cb = nt * 8 + 2 * qid;
            float v0 = sf[nt][0] * 0.125f; if (Ms[rr0 * 64 + cb])     v0 = NEG;
            float v1 = sf[nt][1] * 0.125f; if (Ms[rr0 * 64 + cb + 1]) v1 = NEG;
            float v2 = sf[nt][2] * 0.125f; if (Ms[rr1 * 64 + cb])     v2 = NEG;
            float v3 = sf[nt][3] * 0.125f; if (Ms[rr1 * 64 + cb + 1]) v3 = NEG;
            sf[nt][0] = v0; sf[nt][1] = v1; sf[nt][2] = v2; sf[nt][3] = v3;
            tm0 = fmaxf(tm0, fmaxf(v0, v1));
            tm1 = fmaxf(tm1, fmaxf(v2, v3));
        }
        tm0 = fmaxf(tm0, __shfl_xor_sync(0xffffffffu, tm0, 1));
        tm0 = fmaxf(tm0, __shfl_xor_sync(0xffffffffu, tm0, 2));
        tm1 = fmaxf(tm1, __shfl_xor_sync(0xffffffffu, tm1, 1));
        tm1 = fmaxf(tm1, __shfl_xor_sync(0xffffffffu, tm1, 2));

        const float mn0 = fmaxf(m0, tm0), mn1 = fmaxf(m1, tm1);
        const float cor0 = __expf(m0 - mn0), cor1 = __expf(m1 - mn1);
        m0 = mn0; m1 = mn1;

        float rs0 = 0.f, rs1 = 0.f;
        #pragma unroll
        for (int nt = 0; nt < 8; nt++) {
            float p0 = __expf(sf[nt][0] - m0);
            float p1 = __expf(sf[nt][1] - m0);
            float p2 = __expf(sf[nt][2] - m1);
            float p3 = __expf(sf[nt][3] - m1);
            sf[nt][0] = p0; sf[nt][1] = p1; sf[nt][2] = p2; sf[nt][3] = p3;
            rs0 += p0 + p1; rs1 += p2 + p3;
        }
        rs0 += __shfl_xor_sync(0xffffffffu, rs0, 1);
        rs0 += __shfl_xor_sync(0xffffffffu, rs0, 2);
        rs1 += __shfl_xor_sync(0xffffffffu, rs1, 1);
        rs1 += __shfl_xor_sync(0xffffffffu, rs1, 2);
        l0 = l0 * cor0 + rs0;
        l1 = l1 * cor1 + rs1;

        #pragma unroll
        for (int nt = 0; nt < 8; nt++) {
            o[nt][0] *= cor0; o[nt][1] *= cor0;
            o[nt][2] *= cor1; o[nt][3] *= cor1;
        }

        __syncthreads();  // all K reads done before P overwrite (aliases Kh/Kl)
        #pragma unroll
        for (int nt = 0; nt < 8; nt++) {
            const int cb = nt * 8 + 2 * qid;
            *(float2*)(Ps + rr0 * 68 + cb) = make_float2(ftf32(sf[nt][0]), ftf32(sf[nt][1]));
            *(float2*)(Ps + rr1 * 68 + cb) = make_float2(ftf32(sf[nt][2]), ftf32(sf[nt][3]));
        }
        __syncthreads();

        // O += P @ V (tf32)
        #pragma unroll
        for (int ks = 0; ks < 8; ks++) {
            const int kk = ks * 8;
            uint32_t af[4];
            af[0] = __float_as_uint(Ps[rr0 * 68 + kk + qid]);
            af[1] = __float_as_uint(Ps[rr1 * 68 + kk + qid]);
            af[2] = __float_as_uint(Ps[rr0 * 68 + kk + qid + 4]);
            af[3] = __float_as_uint(Ps[rr1 * 68 + kk + qid + 4]);
            #pragma unroll
            for (int nt = 0; nt < 8; nt++) {
                uint32_t bf[2];
                bf[0] = __float_as_uint(Vs[(kk + qid) * 72 + nt * 8 + grp]);
                bf[1] = __float_as_uint(Vs[(kk + qid + 4) * 72 + nt * 8 + grp]);
                mma8(o[nt], af, bf);
            }
        }
    }

    const float inv0 = 1.f / l0, inv1 = 1.f / l1;
    float* ob = Om + (size_t)b * cS * cE + h * cHD;
    #pragma unroll
    for (int nt = 0; nt < 8; nt++) {
        const int col = nt * 8 + 2 * qid;
        *(float2*)(ob + (size_t)(r0 + rr0) * cE + col) =
            make_float2(o[nt][0] * inv0, o[nt][1] * inv0);
        *(float2*)(ob + (size_t)(r0 + rr1) * cE + col) =
            make_float2(o[nt][2] * inv1, o[nt][3] * inv1);
    }
}

// ---------------- launcher ----------------
extern "C" void kernel_launch(void* const* d_in, const int* in_sizes, int n_in,
                              void* d_out, int out_size)
{
    (void)in_sizes; (void)n_in; (void)out_size;
    const float* q   = (const float*)d_in[0];
    const float* k   = (const float*)d_in[1];
    const float* v   = (const float*)d_in[2];
    const unsigned int* mask_raw = (const unsigned int*)d_in[3];
    const float* Wq  = (const float*)d_in[4];
    const float* bq  = (const float*)d_in[5];
    const float* Wk  = (const float*)d_in[6];
    const float* bk  = (const float*)d_in[7];
    const float* Wv  = (const float*)d_in[8];
    const float* bv  = (const float*)d_in[9];
    const float* Whq = (const float*)d_in[10];
    const float* bhq = (const float*)d_in[11];
    const float* Whk = (const float*)d_in[12];
    const float* bhk = (const float*)d_in[13];
    const float* Whv = (const float*)d_in[14];
    const float* bhv = (const float*)d_in[15];
    const float* Wo  = (const float*)d_in[16];
    const float* bo  = (const float*)d_in[17];
    float* out = (float*)d_out;

    float *p_qg, *p_kg, *p_vg, *p_qh, *p_kh, *p_vh, *p_at;
    unsigned char* p_mask;
    __nv_bfloat16 *wh_q, *wl_q, *wh_k, *wl_k, *wh_v, *wl_v, *wh_o, *wl_o;
    __nv_bfloat16 *wh_hq, *wl_hq, *wh_hk, *wl_hk, *wh_hv, *wl_hv;
    cudaGetSymbolAddress((void**)&p_qg, g_qg);
    cudaGetSymbolAddress((void**)&p_kg, g_kg);
    cudaGetSymbolAddress((void**)&p_vg, g_vg);
    cudaGetSymbolAddress((void**)&p_qh, g_qh);
    cudaGetSymbolAddress((void**)&p_kh, g_kh);
    cudaGetSymbolAddress((void**)&p_vh, g_vh);
    cudaGetSymbolAddress((void**)&p_at, g_at);
    cudaGetSymbolAddress((void**)&p_mask, g_mask);
    cudaGetSymbolAddress((void**)&wh_q, g_wh_q);   cudaGetSymbolAddress((void**)&wl_q, g_wl_q);
    cudaGetSymbolAddress((void**)&wh_k, g_wh_k);   cudaGetSymbolAddress((void**)&wl_k, g_wl_k);
    cudaGetSymbolAddress((void**)&wh_v, g_wh_v);   cudaGetSymbolAddress((void**)&wl_v, g_wl_v);
    cudaGetSymbolAddress((void**)&wh_o, g_wh_o);   cudaGetSymbolAddress((void**)&wl_o, g_wl_o);
    cudaGetSymbolAddress((void**)&wh_hq, g_wh_hq); cudaGetSymbolAddress((void**)&wl_hq, g_wl_hq);
    cudaGetSymbolAddress((void**)&wh_hk, g_wh_hk); cudaGetSymbolAddress((void**)&wl_hk, g_wl_hk);
    cudaGetSymbolAddress((void**)&wh_hv, g_wh_hv); cudaGetSymbolAddress((void**)&wl_hv, g_wl_hv);

    cudaFuncSetAttribute(gemm_bf16x3, cudaFuncAttributeMaxDynamicSharedMemorySize, GSMEM);
    cudaFuncSetAttribute(flash_attn,  cudaFuncAttributeMaxDynamicSharedMemorySize, ASMEM);

    const dim3 gg(8, 32);                 // N/128, M/128
    const dim3 gw(32, 32);                // 32x32 transpose tiles
    const dim3 gwh(2, 32, 16);            // d-tiles, e-tiles, heads

    mask_convert<<<(cB * cS * cS) / 4 / 256, 256>>>(mask_raw, p_mask);

    prep_w<<<gw, 256>>>(Wq, wh_q, wl_q);
    prep_w<<<gw, 256>>>(Wk, wh_k, wl_k);
    prep_w<<<gw, 256>>>(Wv, wh_v, wl_v);
    prep_w<<<gw, 256>>>(Wo, wh_o, wl_o);
    prep_wh<<<gwh, 256>>>(Whq, wh_hq, wl_hq);
    prep_wh<<<gwh, 256>>>(Whk, wh_hk, wl_hk);
    prep_wh<<<gwh, 256>>>(Whv, wh_hv, wl_hv);

    gemm_bf16x3<<<gg, 256, GSMEM>>>(q, wh_q, wl_q, bq, p_qg);
    gemm_bf16x3<<<gg, 256, GSMEM>>>(k, wh_k, wl_k, bk, p_kg);
    gemm_bf16x3<<<gg, 256, GSMEM>>>(v, wh_v, wl_v, bv, p_vg);

    gemm_bf16x3<<<gg, 256, GSMEM>>>(p_qg, wh_hq, wl_hq, bhq, p_qh);
    gemm_bf16x3<<<gg, 256, GSMEM>>>(p_kg, wh_hk, wl_hk, bhk, p_kh);
    gemm_bf16x3<<<gg, 256, GSMEM>>>(p_vg, wh_hv, wl_hv, bhv, p_vh);

    flash_attn<<<dim3(32, 32), 128, ASMEM>>>(p_qh, p_kh, p_vh, p_mask, p_at);

    gemm_bf16x3<<<gg, 256, GSMEM>>>(p_at, wh_o, wl_o, bo, out);
}